// round 14
// baseline (speedup 1.0000x reference)
#include <cuda_runtime.h>
#include <cstdint>
#include <cstring>

#define BB 16
#define NN 128
#define DD 128

#define PREP_BLOCKS 256
#define HHAT_BLOCKS 256   // 16 per batch: (j-chunk of 16) x (d-half of 64)

// Split-K GEMM config (R13-proven)
#define SK  8
#define KB  64
#define SBM 64
#define SBK 16

// Scratch (device globals — allocations forbidden)
__device__ float g_xfull[BB * NN * 512];     // [hhat | deg*h | ehat | h]
__device__ float g_G[512 * 128];
__device__ float g_bb[128];
__device__ float g_deg[BB * NN];
__device__ float g_part[SK * BB * NN * 128];

__device__ __forceinline__ unsigned long long f2ull(float x, float y) {
    float2 v = make_float2(x, y);
    unsigned long long u; memcpy(&u, &v, 8); return u;
}
__device__ __forceinline__ float2 ull2f(unsigned long long u) {
    float2 v; memcpy(&v, &u, 8); return v;
}

// ---------------------------------------------------------------------------
// Fused kernel, 256 threads:
//  [0,256):    prep (G, bb)
//  [256,512):  hhat — lean adj^T@h blocks: 1 float4 acc, 8.5KB smem
//  [512,2560): e-reduce — ehat only (h work fully evicted)
// ---------------------------------------------------------------------------
__global__ void __launch_bounds__(256) fused_prep_reduce(
    const float* __restrict__ h,
    const float* __restrict__ adj,
    const float* __restrict__ e,
    const float* __restrict__ Wm,
    const float* __restrict__ Wu,
    const float* __restrict__ bm,
    float* __restrict__ xfull,
    float* __restrict__ deg_out,
    float* __restrict__ G,
    float* __restrict__ bb)
{
    const int tid  = threadIdx.x;
    const int lane = tid & 31;
    const int w    = tid >> 5;

    if (blockIdx.x < PREP_BLOCKS) {
        // ----------------------- prep path -----------------------
        __shared__ float s_wm[2][128];
        const int pid = blockIdx.x;
        const int c0  = pid * 2;
        const int cl  = tid >> 7;
        const int k   = tid & 127;

        {
            const int q  = tid & 127;
            const int cc = c0 + (tid >> 7);
            s_wm[tid >> 7][q] = (cc < 384) ? Wm[(size_t)q * 384 + cc] : 0.f;
        }
        __syncthreads();

        const int c = c0 + cl;
        if (c < 384) {
            const float* __restrict__ wu = Wu + (size_t)k * 256 + 128;
            float acc = 0.f;
            #pragma unroll 4
            for (int q = 0; q < 128; q += 4) {
                const float4 v = *(const float4*)(wu + q);
                acc += s_wm[cl][q]     * v.x;
                acc += s_wm[cl][q + 1] * v.y;
                acc += s_wm[cl][q + 2] * v.z;
                acc += s_wm[cl][q + 3] * v.w;
            }
            G[(size_t)c * 128 + k] = acc;
        } else {
            G[(size_t)c * 128 + k] = Wu[(size_t)k * 256 + (c - 384)];
        }

        if (pid == 0 && tid < 128) {
            const float* __restrict__ wu = Wu + (size_t)tid * 256 + 128;
            float acc = 0.f;
            #pragma unroll 4
            for (int q = 0; q < 128; q += 4) {
                const float4 v  = *(const float4*)(wu + q);
                const float4 bv = *(const float4*)(bm + q);
                acc += bv.x * v.x + bv.y * v.y + bv.z * v.z + bv.w * v.w;
            }
            bb[tid] = acc;
        }
        return;
    }

    if (blockIdx.x < PREP_BLOCKS + HHAT_BLOCKS) {
        // ----------------------- hhat path (lean) -----------------------
        // Block = (b, 16 j's, 64 d's). hhat[j,d] = sum_i adj[b,i,j]*h[b,i,d]
        __shared__ float s_adjc[NN][17];   // adj[b, :, j0:j0+16], 8.7KB

        const int pid = blockIdx.x - PREP_BLOCKS;  // 0..255
        const int b   = pid >> 4;
        const int sub = pid & 15;
        const int j0  = (sub >> 1) * 16;
        const int dh  = (sub & 1) * 64;            // d offset (floats)
        const int jj  = tid >> 4;                  // 0..15
        const int pos = tid & 15;                  // 0..15

        for (int k = tid; k < NN * 16; k += 256) {
            const int i  = k >> 4;
            const int jc = k & 15;
            s_adjc[i][jc] = adj[((size_t)b * NN + i) * NN + j0 + jc];
        }
        __syncthreads();

        const float* __restrict__ hbase = h + (size_t)b * NN * DD + dh + pos * 4;
        float4 acc = make_float4(0.f, 0.f, 0.f, 0.f);
        float dg = 0.f;
        #pragma unroll 4
        for (int i = 0; i < NN; ++i) {
            const float a = s_adjc[i][jj];
            const float4 hv = *(const float4*)(hbase + (size_t)i * DD);
            dg += a;
            acc.x += a * hv.x; acc.y += a * hv.y;
            acc.z += a * hv.z; acc.w += a * hv.w;
        }

        const int r = b * NN + j0 + jj;
        const float4 hv = *(const float4*)(h + (size_t)r * DD + dh + pos * 4);
        *(float4*)(xfull + (size_t)r * 512 + dh + pos * 4)       = acc;      // hhat
        *(float4*)(xfull + (size_t)r * 512 + 128 + dh + pos * 4) =
            make_float4(dg * hv.x, dg * hv.y, dg * hv.z, dg * hv.w);         // deg*h
        *(float4*)(xfull + (size_t)r * 512 + 384 + dh + pos * 4) = hv;       // h
        if (pos == 0 && dh == 0) deg_out[r] = dg;
        return;
    }

    // ----------------------- e-reduce path (ehat only) -----------------------
    const int rid = blockIdx.x - (PREP_BLOCKS + HHAT_BLOCKS);
    const int j = rid & (NN - 1);
    const int b = rid >> 7;

    __shared__ __align__(16) float s_re[8][DD];
    __shared__ float    s_val[NN];
    __shared__ int      s_idx[NN];
    __shared__ unsigned s_ball[4];
    __shared__ int      s_cnt;

    float a = 0.f;
    if (tid < NN) {
        a = adj[((size_t)b * NN + tid) * NN + j];
        unsigned ball = __ballot_sync(0xffffffffu, a != 0.f);
        if (lane == 0) s_ball[w] = ball;
    }
    __syncthreads();
    if (tid < NN) {
        int base = 0;
        #pragma unroll
        for (int ww = 0; ww < 4; ++ww) if (ww < w) base += __popc(s_ball[ww]);
        const unsigned ball = s_ball[w];
        if (a != 0.f) {
            const int pos = base + __popc(ball & ((1u << lane) - 1u));
            s_idx[pos] = tid;
            s_val[pos] = a;
        }
        if (tid == 0)
            s_cnt = __popc(s_ball[0]) + __popc(s_ball[1]) + __popc(s_ball[2]) + __popc(s_ball[3]);
    }
    __syncthreads();

    const int cnt = s_cnt;

    // e[b,i,j,d]: base (i=0) = (b*NN*NN + j)*DD ; stride over i = NN*DD
    const float* __restrict__ eb = e + ((size_t)b * NN * NN + (size_t)j) * DD + lane * 4;

    float4 ae = make_float4(0.f, 0.f, 0.f, 0.f);
    #pragma unroll 4
    for (int t = w; t < cnt; t += 8) {
        const float aa = s_val[t];
        const float4 ev = __ldcs((const float4*)(eb + (size_t)s_idx[t] * (NN * DD)));
        ae.x += aa * ev.x; ae.y += aa * ev.y; ae.z += aa * ev.z; ae.w += aa * ev.w;
    }
    *(float4*)&s_re[w][lane * 4] = ae;
    __syncthreads();

    if (tid < NN) {
        float se = 0.f;
        #pragma unroll
        for (int ww = 0; ww < 8; ++ww) se += s_re[ww][tid];
        const size_t r = (size_t)b * NN + j;
        xfull[r * 512 + 256 + tid] = se;   // ehat
    }
}

// ---------------------------------------------------------------------------
// Split-K GEMM (R13-proven): 128 threads, tile 64x128, TM=8 x TN=8.
// ---------------------------------------------------------------------------
__global__ void __launch_bounds__(128) gemm_split(
    const float* __restrict__ A,     // 2048 x 512
    const float* __restrict__ G,     // 512 x 128
    float* __restrict__ part)        // SK x 2048 x 128
{
    __shared__ __align__(16) float As[SBK][68];
    __shared__ __align__(16) float Bs[SBK][128];

    const int ks  = blockIdx.x;
    const int m0  = blockIdx.y * SBM;
    const int kb  = ks * KB;
    const int tid = threadIdx.x;
    const int tx  = tid & 15;
    const int ty  = tid >> 4;

    const int am = tid >> 1;
    const int ak = (tid & 1) * 8;
    const int bk = tid >> 3;
    const int bc = (tid & 7) * 16;

    unsigned long long acc[8][4];
    #pragma unroll
    for (int i = 0; i < 8; ++i)
        #pragma unroll
        for (int jj = 0; jj < 4; ++jj) acc[i][jj] = 0ull;

    for (int t = 0; t < KB; t += SBK) {
        {
            const float* ar = A + (size_t)(m0 + am) * 512 + kb + t + ak;
            const float4 a0 = *(const float4*)(ar);
            const float4 a1 = *(const float4*)(ar + 4);
            As[ak + 0][am] = a0.x; As[ak + 1][am] = a0.y;
            As[ak + 2][am] = a0.z; As[ak + 3][am] = a0.w;
            As[ak + 4][am] = a1.x; As[ak + 5][am] = a1.y;
            As[ak + 6][am] = a1.z; As[ak + 7][am] = a1.w;
        }
        {
            const float* gr = G + (size_t)(kb + t + bk) * 128 + bc;
            *(float4*)&Bs[bk][bc]      = *(const float4*)(gr);
            *(float4*)&Bs[bk][bc + 4]  = *(const float4*)(gr + 4);
            *(float4*)&Bs[bk][bc + 8]  = *(const float4*)(gr + 8);
            *(float4*)&Bs[bk][bc + 12] = *(const float4*)(gr + 12);
        }
        __syncthreads();

        #pragma unroll
        for (int kk = 0; kk < SBK; ++kk) {
            const float4 pa0 = *(const float4*)&As[kk][ty * 8];
            const float4 pa1 = *(const float4*)&As[kk][ty * 8 + 4];
            const float4 pb0 = *(const float4*)&Bs[kk][tx * 8];
            const float4 pb1 = *(const float4*)&Bs[kk][tx * 8 + 4];
            unsigned long long amv[8], bnv[4];
            amv[0] = f2ull(pa0.x, pa0.x); amv[1] = f2ull(pa0.y, pa0.y);
            amv[2] = f2ull(pa0.z, pa0.z); amv[3] = f2ull(pa0.w, pa0.w);
            amv[4] = f2ull(pa1.x, pa1.x); amv[5] = f2ull(pa1.y, pa1.y);
            amv[6] = f2ull(pa1.z, pa1.z); amv[7] = f2ull(pa1.w, pa1.w);
            bnv[0] = f2ull(pb0.x, pb0.y); bnv[1] = f2ull(pb0.z, pb0.w);
            bnv[2] = f2ull(pb1.x, pb1.y); bnv[3] = f2ull(pb1.z, pb1.w);
            #pragma unroll
            for (int i = 0; i < 8; ++i)
                #pragma unroll
                for (int jj = 0; jj < 4; ++jj)
                    asm("fma.rn.f32x2 %0, %1, %2, %0;"
                        : "+l"(acc[i][jj]) : "l"(amv[i]), "l"(bnv[jj]));
        }
        __syncthreads();
    }

    float* p = part + (size_t)ks * (BB * NN * 128);
    #pragma unroll
    for (int i = 0; i < 8; ++i) {
        const int row = m0 + ty * 8 + i;
        const float2 v0 = ull2f(acc[i][0]);
        const float2 v1 = ull2f(acc[i][1]);
        const float2 v2 = ull2f(acc[i][2]);
        const float2 v3 = ull2f(acc[i][3]);
        *(float4*)(p + (size_t)row * 128 + tx * 8)     = make_float4(v0.x, v0.y, v1.x, v1.y);
        *(float4*)(p + (size_t)row * 128 + tx * 8 + 4) = make_float4(v2.x, v2.y, v3.x, v3.y);
    }
}

// ---------------------------------------------------------------------------
// finish: C = sum_ks part[ks] + deg⊗bb + bu   (part is L2-resident)
// ---------------------------------------------------------------------------
__global__ void __launch_bounds__(128) finish_kernel(
    const float* __restrict__ part,
    const float* __restrict__ bb,
    const float* __restrict__ bu,
    const float* __restrict__ deg,
    float* __restrict__ C)
{
    const int t   = blockIdx.x * 128 + threadIdx.x;
    const int row = t >> 5;
    const int c4  = (t & 31) * 4;
    const size_t off = (size_t)row * 128 + c4;

    float4 s = make_float4(0.f, 0.f, 0.f, 0.f);
    #pragma unroll
    for (int ks = 0; ks < SK; ++ks) {
        const float4 v = *(const float4*)(part + (size_t)ks * (BB * NN * 128) + off);
        s.x += v.x; s.y += v.y; s.z += v.z; s.w += v.w;
    }
    const float dg = __ldg(deg + row);
    const float4 bbv = *(const float4*)(bb + c4);
    const float4 buv = *(const float4*)(bu + c4);
    s.x += dg * bbv.x + buv.x;
    s.y += dg * bbv.y + buv.y;
    s.z += dg * bbv.z + buv.z;
    s.w += dg * bbv.w + buv.w;
    *(float4*)(C + off) = s;
}

// ---------------------------------------------------------------------------
// kernel_launch: inputs: h, adj, e, Wm, bm, Wu, bu ; output (B,N,D) fp32
// ---------------------------------------------------------------------------
extern "C" void kernel_launch(void* const* d_in, const int* in_sizes, int n_in,
                              void* d_out, int out_size)
{
    const float* h   = (const float*)d_in[0];
    const float* adj = (const float*)d_in[1];
    const float* e   = (const float*)d_in[2];
    const float* Wm  = (const float*)d_in[3];
    const float* bm  = (const float*)d_in[4];
    const float* Wu  = (const float*)d_in[5];
    const float* bu  = (const float*)d_in[6];
    float* out = (float*)d_out;

    float* xfull; cudaGetSymbolAddress((void**)&xfull, g_xfull);
    float* G;     cudaGetSymbolAddress((void**)&G,     g_G);
    float* bb;    cudaGetSymbolAddress((void**)&bb,    g_bb);
    float* deg;   cudaGetSymbolAddress((void**)&deg,   g_deg);
    float* part;  cudaGetSymbolAddress((void**)&part,  g_part);

    fused_prep_reduce<<<PREP_BLOCKS + HHAT_BLOCKS + BB * NN, 256>>>(
        h, adj, e, Wm, Wu, bm, xfull, deg, G, bb);

    {
        dim3 grid(SK, (BB * NN) / SBM);   // (8, 32)
        gemm_split<<<grid, 128>>>(xfull, G, part);
    }
    finish_kernel<<<512, 128>>>(part, bb, bu, deg, out);
}

// round 15
// speedup vs baseline: 1.0801x; 1.0801x over previous
#include <cuda_runtime.h>
#include <cstdint>
#include <cstring>

#define BB 16
#define NN 128
#define DD 128

#define PREP_BLOCKS 256

// Split-K GEMM config
#define SK  8
#define KB  64
#define SBM 64
#define SBK 16

// Scratch (device globals — allocations forbidden)
__device__ float g_xfull[BB * NN * 512];     // [hhat | deg*h | ehat | h]
__device__ float g_G[512 * 128];
__device__ float g_bb[128];
__device__ float g_deg[BB * NN];
__device__ float g_part[SK * BB * NN * 128];

__device__ __forceinline__ unsigned long long f2ull(float x, float y) {
    float2 v = make_float2(x, y);
    unsigned long long u; memcpy(&u, &v, 8); return u;
}
__device__ __forceinline__ float2 ull2f(unsigned long long u) {
    float2 v; memcpy(&v, &u, 8); return v;
}

// ---------------------------------------------------------------------------
// Fused kernel — FROZEN R7/R13 reduce (25.4us, regs 32, occ 88%).
// [0,256) prep ; [256, 2304) e+h reduce.
// ---------------------------------------------------------------------------
__global__ void __launch_bounds__(256) fused_prep_reduce(
    const float* __restrict__ h,
    const float* __restrict__ adj,
    const float* __restrict__ e,
    const float* __restrict__ Wm,
    const float* __restrict__ Wu,
    const float* __restrict__ bm,
    float* __restrict__ xfull,
    float* __restrict__ deg_out,
    float* __restrict__ G,
    float* __restrict__ bb)
{
    const int tid  = threadIdx.x;
    const int lane = tid & 31;
    const int w    = tid >> 5;

    if (blockIdx.x < PREP_BLOCKS) {
        // ----------------------- prep path -----------------------
        __shared__ float s_wm[2][128];
        const int pid = blockIdx.x;
        const int c0  = pid * 2;
        const int cl  = tid >> 7;
        const int k   = tid & 127;

        {
            const int q  = tid & 127;
            const int cc = c0 + (tid >> 7);
            s_wm[tid >> 7][q] = (cc < 384) ? Wm[(size_t)q * 384 + cc] : 0.f;
        }
        __syncthreads();

        const int c = c0 + cl;
        if (c < 384) {
            const float* __restrict__ wu = Wu + (size_t)k * 256 + 128;
            float acc = 0.f;
            #pragma unroll 4
            for (int q = 0; q < 128; q += 4) {
                const float4 v = *(const float4*)(wu + q);
                acc += s_wm[cl][q]     * v.x;
                acc += s_wm[cl][q + 1] * v.y;
                acc += s_wm[cl][q + 2] * v.z;
                acc += s_wm[cl][q + 3] * v.w;
            }
            G[(size_t)c * 128 + k] = acc;
        } else {
            G[(size_t)c * 128 + k] = Wu[(size_t)k * 256 + (c - 384)];
        }

        if (pid == 0 && tid < 128) {
            const float* __restrict__ wu = Wu + (size_t)tid * 256 + 128;
            float acc = 0.f;
            #pragma unroll 4
            for (int q = 0; q < 128; q += 4) {
                const float4 v  = *(const float4*)(wu + q);
                const float4 bv = *(const float4*)(bm + q);
                acc += bv.x * v.x + bv.y * v.y + bv.z * v.z + bv.w * v.w;
            }
            bb[tid] = acc;
        }
        return;
    }

    // ----------------------- reduce path (FROZEN) -----------------------
    const int rid = blockIdx.x - PREP_BLOCKS;
    const int j = rid & (NN - 1);
    const int b = rid >> 7;

    __shared__ __align__(16) float s_re[8][DD];
    __shared__ __align__(16) float s_rh[8][DD];
    __shared__ float    s_val[NN];
    __shared__ int      s_idx[NN];
    __shared__ unsigned s_ball[4];
    __shared__ float    s_wsum[4];
    __shared__ int      s_cnt;
    __shared__ float    s_deg;

    float a = 0.f;
    if (tid < NN) {
        a = adj[((size_t)b * NN + tid) * NN + j];
        unsigned ball = __ballot_sync(0xffffffffu, a != 0.f);
        float s = a;
        #pragma unroll
        for (int off = 16; off; off >>= 1) s += __shfl_down_sync(0xffffffffu, s, off);
        if (lane == 0) { s_ball[w] = ball; s_wsum[w] = s; }
    }
    __syncthreads();
    if (tid < NN) {
        int base = 0;
        #pragma unroll
        for (int ww = 0; ww < 4; ++ww) if (ww < w) base += __popc(s_ball[ww]);
        const unsigned ball = s_ball[w];
        if (a != 0.f) {
            const int pos = base + __popc(ball & ((1u << lane) - 1u));
            s_idx[pos] = tid;
            s_val[pos] = a;
        }
        if (tid == 0) {
            s_cnt = __popc(s_ball[0]) + __popc(s_ball[1]) + __popc(s_ball[2]) + __popc(s_ball[3]);
            s_deg = s_wsum[0] + s_wsum[1] + s_wsum[2] + s_wsum[3];
        }
    }
    __syncthreads();

    const int cnt = s_cnt;
    const float deg = s_deg;

    // e[b,i,j,d]: base (i=0) = (b*NN*NN + j)*DD ; stride over i = NN*DD
    const float* __restrict__ eb = e + ((size_t)b * NN * NN + (size_t)j) * DD + lane * 4;
    const float* __restrict__ hb = h + (size_t)b * NN * DD + lane * 4;

    float4 ae = make_float4(0.f, 0.f, 0.f, 0.f);
    float4 ah = make_float4(0.f, 0.f, 0.f, 0.f);
    #pragma unroll 4
    for (int t = w; t < cnt; t += 8) {
        const float aa = s_val[t];
        const int   i  = s_idx[t];
        const float4 ev = *(const float4*)(eb + (size_t)i * (NN * DD));
        const float4 hv = *(const float4*)(hb + (size_t)i * DD);
        ae.x += aa * ev.x; ae.y += aa * ev.y; ae.z += aa * ev.z; ae.w += aa * ev.w;
        ah.x += aa * hv.x; ah.y += aa * hv.y; ah.z += aa * hv.z; ah.w += aa * hv.w;
    }
    *(float4*)&s_re[w][lane * 4] = ae;
    *(float4*)&s_rh[w][lane * 4] = ah;
    __syncthreads();

    if (tid < NN) {
        float se = 0.f, sh = 0.f;
        #pragma unroll
        for (int ww = 0; ww < 8; ++ww) { se += s_re[ww][tid]; sh += s_rh[ww][tid]; }
        const size_t r  = (size_t)b * NN + j;
        const float  hv = h[r * DD + tid];
        xfull[r * 512 + tid]       = sh;        // hhat
        xfull[r * 512 + 128 + tid] = deg * hv;  // deg*h
        xfull[r * 512 + 256 + tid] = se;        // ehat
        xfull[r * 512 + 384 + tid] = hv;        // h
        if (tid == 0) deg_out[r] = deg;
    }
}

// ---------------------------------------------------------------------------
// Split-K GEMM with register-prefetch double buffering.
// 128 threads, tile 64x128, TM=8 x TN=8, grid (8, 32).
// Stage t+1's GMEM loads issue before stage t's compute -> latency hidden.
// ---------------------------------------------------------------------------
__global__ void __launch_bounds__(128) gemm_split(
    const float* __restrict__ A,     // 2048 x 512
    const float* __restrict__ G,     // 512 x 128
    float* __restrict__ part)        // SK x 2048 x 128
{
    __shared__ __align__(16) float As[SBK][68];
    __shared__ __align__(16) float Bs[SBK][128];

    const int ks  = blockIdx.x;
    const int m0  = blockIdx.y * SBM;
    const int kb  = ks * KB;
    const int tid = threadIdx.x;
    const int tx  = tid & 15;
    const int ty  = tid >> 4;

    const int am = tid >> 1;          // 0..63
    const int ak = (tid & 1) * 8;     // 0, 8
    const int bk = tid >> 3;          // 0..15
    const int bc = (tid & 7) * 16;    // 0..112

    const float* __restrict__ arp = A + (size_t)(m0 + am) * 512 + kb + ak;
    const float* __restrict__ grp = G + (size_t)(kb + bk) * 128 + bc;

    unsigned long long acc[8][4];
    #pragma unroll
    for (int i = 0; i < 8; ++i)
        #pragma unroll
        for (int jj = 0; jj < 4; ++jj) acc[i][jj] = 0ull;

    // Prefetch stage 0
    float4 pa0 = *(const float4*)(arp);
    float4 pa1 = *(const float4*)(arp + 4);
    float4 pg0 = *(const float4*)(grp);
    float4 pg1 = *(const float4*)(grp + 4);
    float4 pg2 = *(const float4*)(grp + 8);
    float4 pg3 = *(const float4*)(grp + 12);

    for (int t = 0; t < KB; t += SBK) {
        // Commit prefetched stage to smem
        As[ak + 0][am] = pa0.x; As[ak + 1][am] = pa0.y;
        As[ak + 2][am] = pa0.z; As[ak + 3][am] = pa0.w;
        As[ak + 4][am] = pa1.x; As[ak + 5][am] = pa1.y;
        As[ak + 6][am] = pa1.z; As[ak + 7][am] = pa1.w;
        *(float4*)&Bs[bk][bc]      = pg0;
        *(float4*)&Bs[bk][bc + 4]  = pg1;
        *(float4*)&Bs[bk][bc + 8]  = pg2;
        *(float4*)&Bs[bk][bc + 12] = pg3;
        __syncthreads();

        // Issue next stage's loads BEFORE compute (latency overlaps FMAs)
        if (t + SBK < KB) {
            const float* ar = arp + t + SBK;
            const float* gr = grp + (size_t)(t + SBK) * 128;
            pa0 = *(const float4*)(ar);
            pa1 = *(const float4*)(ar + 4);
            pg0 = *(const float4*)(gr);
            pg1 = *(const float4*)(gr + 4);
            pg2 = *(const float4*)(gr + 8);
            pg3 = *(const float4*)(gr + 12);
        }

        #pragma unroll
        for (int kk = 0; kk < SBK; ++kk) {
            const float4 qa0 = *(const float4*)&As[kk][ty * 8];
            const float4 qa1 = *(const float4*)&As[kk][ty * 8 + 4];
            const float4 qb0 = *(const float4*)&Bs[kk][tx * 8];
            const float4 qb1 = *(const float4*)&Bs[kk][tx * 8 + 4];
            unsigned long long amv[8], bnv[4];
            amv[0] = f2ull(qa0.x, qa0.x); amv[1] = f2ull(qa0.y, qa0.y);
            amv[2] = f2ull(qa0.z, qa0.z); amv[3] = f2ull(qa0.w, qa0.w);
            amv[4] = f2ull(qa1.x, qa1.x); amv[5] = f2ull(qa1.y, qa1.y);
            amv[6] = f2ull(qa1.z, qa1.z); amv[7] = f2ull(qa1.w, qa1.w);
            bnv[0] = f2ull(qb0.x, qb0.y); bnv[1] = f2ull(qb0.z, qb0.w);
            bnv[2] = f2ull(qb1.x, qb1.y); bnv[3] = f2ull(qb1.z, qb1.w);
            #pragma unroll
            for (int i = 0; i < 8; ++i)
                #pragma unroll
                for (int jj = 0; jj < 4; ++jj)
                    asm("fma.rn.f32x2 %0, %1, %2, %0;"
                        : "+l"(acc[i][jj]) : "l"(amv[i]), "l"(bnv[jj]));
        }
        __syncthreads();
    }

    float* p = part + (size_t)ks * (BB * NN * 128);
    #pragma unroll
    for (int i = 0; i < 8; ++i) {
        const int row = m0 + ty * 8 + i;
        const float2 v0 = ull2f(acc[i][0]);
        const float2 v1 = ull2f(acc[i][1]);
        const float2 v2 = ull2f(acc[i][2]);
        const float2 v3 = ull2f(acc[i][3]);
        *(float4*)(p + (size_t)row * 128 + tx * 8)     = make_float4(v0.x, v0.y, v1.x, v1.y);
        *(float4*)(p + (size_t)row * 128 + tx * 8 + 4) = make_float4(v2.x, v2.y, v3.x, v3.y);
    }
}

// ---------------------------------------------------------------------------
// finish: C = sum_ks part[ks] + deg⊗bb + bu   (part is L2-resident)
// ---------------------------------------------------------------------------
__global__ void __launch_bounds__(128) finish_kernel(
    const float* __restrict__ part,
    const float* __restrict__ bb,
    const float* __restrict__ bu,
    const float* __restrict__ deg,
    float* __restrict__ C)
{
    const int t   = blockIdx.x * 128 + threadIdx.x;
    const int row = t >> 5;
    const int c4  = (t & 31) * 4;
    const size_t off = (size_t)row * 128 + c4;

    float4 s = make_float4(0.f, 0.f, 0.f, 0.f);
    #pragma unroll
    for (int ks = 0; ks < SK; ++ks) {
        const float4 v = *(const float4*)(part + (size_t)ks * (BB * NN * 128) + off);
        s.x += v.x; s.y += v.y; s.z += v.z; s.w += v.w;
    }
    const float dg = __ldg(deg + row);
    const float4 bbv = *(const float4*)(bb + c4);
    const float4 buv = *(const float4*)(bu + c4);
    s.x += dg * bbv.x + buv.x;
    s.y += dg * bbv.y + buv.y;
    s.z += dg * bbv.z + buv.z;
    s.w += dg * bbv.w + buv.w;
    *(float4*)(C + off) = s;
}

// ---------------------------------------------------------------------------
// kernel_launch: inputs: h, adj, e, Wm, bm, Wu, bu ; output (B,N,D) fp32
// ---------------------------------------------------------------------------
extern "C" void kernel_launch(void* const* d_in, const int* in_sizes, int n_in,
                              void* d_out, int out_size)
{
    const float* h   = (const float*)d_in[0];
    const float* adj = (const float*)d_in[1];
    const float* e   = (const float*)d_in[2];
    const float* Wm  = (const float*)d_in[3];
    const float* bm  = (const float*)d_in[4];
    const float* Wu  = (const float*)d_in[5];
    const float* bu  = (const float*)d_in[6];
    float* out = (float*)d_out;

    float* xfull; cudaGetSymbolAddress((void**)&xfull, g_xfull);
    float* G;     cudaGetSymbolAddress((void**)&G,     g_G);
    float* bb;    cudaGetSymbolAddress((void**)&bb,    g_bb);
    float* deg;   cudaGetSymbolAddress((void**)&deg,   g_deg);
    float* part;  cudaGetSymbolAddress((void**)&part,  g_part);

    fused_prep_reduce<<<PREP_BLOCKS + BB * NN, 256>>>(
        h, adj, e, Wm, Wu, bm, xfull, deg, G, bb);

    {
        dim3 grid(SK, (BB * NN) / SBM);   // (8, 32)
        gemm_split<<<grid, 128>>>(xfull, G, part);
    }
    finish_kernel<<<512, 128>>>(part, bb, bu, deg, out);
}

// round 16
// speedup vs baseline: 1.1721x; 1.0851x over previous
#include <cuda_runtime.h>
#include <cstdint>
#include <cstring>

#define BB 16
#define NN 128
#define DD 128

#define PREP_BLOCKS 256

// Split-K GEMM config
#define SK  8
#define KB  64

// Scratch (device globals — allocations forbidden)
__device__ float g_xfull[BB * NN * 512];     // [hhat | deg*h | ehat | h]
__device__ float g_G[512 * 128];
__device__ float g_bb[128];
__device__ float g_deg[BB * NN];
__device__ float g_part[SK * BB * NN * 128];

// ---------------------------------------------------------------------------
// Fused kernel — FROZEN R7/R13 reduce (25.4us, regs 32, occ 88%).
// [0,256) prep ; [256, 2304) e+h reduce.
// ---------------------------------------------------------------------------
__global__ void __launch_bounds__(256) fused_prep_reduce(
    const float* __restrict__ h,
    const float* __restrict__ adj,
    const float* __restrict__ e,
    const float* __restrict__ Wm,
    const float* __restrict__ Wu,
    const float* __restrict__ bm,
    float* __restrict__ xfull,
    float* __restrict__ deg_out,
    float* __restrict__ G,
    float* __restrict__ bb)
{
    const int tid  = threadIdx.x;
    const int lane = tid & 31;
    const int w    = tid >> 5;

    if (blockIdx.x < PREP_BLOCKS) {
        // ----------------------- prep path -----------------------
        __shared__ float s_wm[2][128];
        const int pid = blockIdx.x;
        const int c0  = pid * 2;
        const int cl  = tid >> 7;
        const int k   = tid & 127;

        {
            const int q  = tid & 127;
            const int cc = c0 + (tid >> 7);
            s_wm[tid >> 7][q] = (cc < 384) ? Wm[(size_t)q * 384 + cc] : 0.f;
        }
        __syncthreads();

        const int c = c0 + cl;
        if (c < 384) {
            const float* __restrict__ wu = Wu + (size_t)k * 256 + 128;
            float acc = 0.f;
            #pragma unroll 4
            for (int q = 0; q < 128; q += 4) {
                const float4 v = *(const float4*)(wu + q);
                acc += s_wm[cl][q]     * v.x;
                acc += s_wm[cl][q + 1] * v.y;
                acc += s_wm[cl][q + 2] * v.z;
                acc += s_wm[cl][q + 3] * v.w;
            }
            G[(size_t)c * 128 + k] = acc;
        } else {
            G[(size_t)c * 128 + k] = Wu[(size_t)k * 256 + (c - 384)];
        }

        if (pid == 0 && tid < 128) {
            const float* __restrict__ wu = Wu + (size_t)tid * 256 + 128;
            float acc = 0.f;
            #pragma unroll 4
            for (int q = 0; q < 128; q += 4) {
                const float4 v  = *(const float4*)(wu + q);
                const float4 bv = *(const float4*)(bm + q);
                acc += bv.x * v.x + bv.y * v.y + bv.z * v.z + bv.w * v.w;
            }
            bb[tid] = acc;
        }
        return;
    }

    // ----------------------- reduce path (FROZEN) -----------------------
    const int rid = blockIdx.x - PREP_BLOCKS;
    const int j = rid & (NN - 1);
    const int b = rid >> 7;

    __shared__ __align__(16) float s_re[8][DD];
    __shared__ __align__(16) float s_rh[8][DD];
    __shared__ float    s_val[NN];
    __shared__ int      s_idx[NN];
    __shared__ unsigned s_ball[4];
    __shared__ float    s_wsum[4];
    __shared__ int      s_cnt;
    __shared__ float    s_deg;

    float a = 0.f;
    if (tid < NN) {
        a = adj[((size_t)b * NN + tid) * NN + j];
        unsigned ball = __ballot_sync(0xffffffffu, a != 0.f);
        float s = a;
        #pragma unroll
        for (int off = 16; off; off >>= 1) s += __shfl_down_sync(0xffffffffu, s, off);
        if (lane == 0) { s_ball[w] = ball; s_wsum[w] = s; }
    }
    __syncthreads();
    if (tid < NN) {
        int base = 0;
        #pragma unroll
        for (int ww = 0; ww < 4; ++ww) if (ww < w) base += __popc(s_ball[ww]);
        const unsigned ball = s_ball[w];
        if (a != 0.f) {
            const int pos = base + __popc(ball & ((1u << lane) - 1u));
            s_idx[pos] = tid;
            s_val[pos] = a;
        }
        if (tid == 0) {
            s_cnt = __popc(s_ball[0]) + __popc(s_ball[1]) + __popc(s_ball[2]) + __popc(s_ball[3]);
            s_deg = s_wsum[0] + s_wsum[1] + s_wsum[2] + s_wsum[3];
        }
    }
    __syncthreads();

    const int cnt = s_cnt;
    const float deg = s_deg;

    // e[b,i,j,d]: base (i=0) = (b*NN*NN + j)*DD ; stride over i = NN*DD
    const float* __restrict__ eb = e + ((size_t)b * NN * NN + (size_t)j) * DD + lane * 4;
    const float* __restrict__ hb = h + (size_t)b * NN * DD + lane * 4;

    float4 ae = make_float4(0.f, 0.f, 0.f, 0.f);
    float4 ah = make_float4(0.f, 0.f, 0.f, 0.f);
    #pragma unroll 4
    for (int t = w; t < cnt; t += 8) {
        const float aa = s_val[t];
        const int   i  = s_idx[t];
        const float4 ev = *(const float4*)(eb + (size_t)i * (NN * DD));
        const float4 hv = *(const float4*)(hb + (size_t)i * DD);
        ae.x += aa * ev.x; ae.y += aa * ev.y; ae.z += aa * ev.z; ae.w += aa * ev.w;
        ah.x += aa * hv.x; ah.y += aa * hv.y; ah.z += aa * hv.z; ah.w += aa * hv.w;
    }
    *(float4*)&s_re[w][lane * 4] = ae;
    *(float4*)&s_rh[w][lane * 4] = ah;
    __syncthreads();

    if (tid < NN) {
        float se = 0.f, sh = 0.f;
        #pragma unroll
        for (int ww = 0; ww < 8; ++ww) { se += s_re[ww][tid]; sh += s_rh[ww][tid]; }
        const size_t r  = (size_t)b * NN + j;
        const float  hv = h[r * DD + tid];
        xfull[r * 512 + tid]       = sh;        // hhat
        xfull[r * 512 + 128 + tid] = deg * hv;  // deg*h
        xfull[r * 512 + 256 + tid] = se;        // ehat
        xfull[r * 512 + 384 + tid] = hv;        // h
        if (tid == 0) deg_out[r] = deg;
    }
}

// ---------------------------------------------------------------------------
// Split-K GEMM on tensor cores: tf32 mma.sync with hi/lo error compensation.
// Grid (8, 32), 128 threads (4 warps). Tile 64x128, KB=64, 4 stages of 16.
// Warp w owns rows [w*16, w*16+16), all 128 cols (16 ntiles of m16n8).
// out = ah*bh + ah*bl + al*bh  (al*bl dropped: ~2^-20 rel err)
// ---------------------------------------------------------------------------
__device__ __forceinline__ float tf32hi(float x) {
    return __uint_as_float(__float_as_uint(x) & 0xffffe000u);
}

#define MMA_TF32(c, a0, a1, a2, a3, b0, b1)                                  \
    asm("mma.sync.aligned.m16n8k8.row.col.f32.tf32.tf32.f32 "                \
        "{%0,%1,%2,%3}, {%4,%5,%6,%7}, {%8,%9}, {%0,%1,%2,%3};"              \
        : "+f"((c)[0]), "+f"((c)[1]), "+f"((c)[2]), "+f"((c)[3])             \
        : "r"(a0), "r"(a1), "r"(a2), "r"(a3), "r"(b0), "r"(b1))

__global__ void __launch_bounds__(128) gemm_mma(
    const float* __restrict__ A,     // 2048 x 512 (xfull)
    const float* __restrict__ G,     // 512 x 128
    float* __restrict__ part)        // SK x 2048 x 128
{
    __shared__ __align__(16) float As_h[64][20];   // stride 20: conflict-free frags
    __shared__ __align__(16) float As_l[64][20];
    __shared__ __align__(16) float Bs_h[16][136];  // stride 136: t*8+g distinct banks
    __shared__ __align__(16) float Bs_l[16][136];

    const int ks  = blockIdx.x;
    const int m0  = blockIdx.y * 64;
    const int kb  = ks * KB;
    const int tid = threadIdx.x;
    const int lane = tid & 31;
    const int w    = tid >> 5;
    const int g    = lane >> 2;   // 0..7
    const int t    = lane & 3;    // 0..3

    // staging indices
    const int am  = tid >> 1;          // 0..63  (A row)
    const int ak8 = (tid & 1) * 8;     // 0, 8   (A k-offset within stage)
    const int gk  = tid >> 4;          // 0..7   (G row; also gk+8)
    const int gn  = (tid & 15) * 8;    // 0..120 (G col)

    const float* aptr = A + (size_t)(m0 + am) * 512 + kb + ak8;
    const float* gptr = G + (size_t)(kb + gk) * 128 + gn;

    float acc[16][4];
    #pragma unroll
    for (int nt = 0; nt < 16; ++nt)
        #pragma unroll
        for (int q = 0; q < 4; ++q) acc[nt][q] = 0.f;

    // Prefetch stage 0 (raw fp32)
    float4 ra0 = *(const float4*)(aptr);
    float4 ra1 = *(const float4*)(aptr + 4);
    float4 rg00 = *(const float4*)(gptr);
    float4 rg01 = *(const float4*)(gptr + 4);
    float4 rg10 = *(const float4*)(gptr + (size_t)8 * 128);
    float4 rg11 = *(const float4*)(gptr + (size_t)8 * 128 + 4);

    #pragma unroll
    for (int s = 0; s < 4; ++s) {
        // Convert (hi = tf32-truncate, lo = residual) and commit to smem
        {
            float4 hi, lo;
            hi.x = tf32hi(ra0.x); lo.x = ra0.x - hi.x;
            hi.y = tf32hi(ra0.y); lo.y = ra0.y - hi.y;
            hi.z = tf32hi(ra0.z); lo.z = ra0.z - hi.z;
            hi.w = tf32hi(ra0.w); lo.w = ra0.w - hi.w;
            *(float4*)&As_h[am][ak8] = hi;
            *(float4*)&As_l[am][ak8] = lo;
            hi.x = tf32hi(ra1.x); lo.x = ra1.x - hi.x;
            hi.y = tf32hi(ra1.y); lo.y = ra1.y - hi.y;
            hi.z = tf32hi(ra1.z); lo.z = ra1.z - hi.z;
            hi.w = tf32hi(ra1.w); lo.w = ra1.w - hi.w;
            *(float4*)&As_h[am][ak8 + 4] = hi;
            *(float4*)&As_l[am][ak8 + 4] = lo;

            hi.x = tf32hi(rg00.x); lo.x = rg00.x - hi.x;
            hi.y = tf32hi(rg00.y); lo.y = rg00.y - hi.y;
            hi.z = tf32hi(rg00.z); lo.z = rg00.z - hi.z;
            hi.w = tf32hi(rg00.w); lo.w = rg00.w - hi.w;
            *(float4*)&Bs_h[gk][gn] = hi;
            *(float4*)&Bs_l[gk][gn] = lo;
            hi.x = tf32hi(rg01.x); lo.x = rg01.x - hi.x;
            hi.y = tf32hi(rg01.y); lo.y = rg01.y - hi.y;
            hi.z = tf32hi(rg01.z); lo.z = rg01.z - hi.z;
            hi.w = tf32hi(rg01.w); lo.w = rg01.w - hi.w;
            *(float4*)&Bs_h[gk][gn + 4] = hi;
            *(float4*)&Bs_l[gk][gn + 4] = lo;
            hi.x = tf32hi(rg10.x); lo.x = rg10.x - hi.x;
            hi.y = tf32hi(rg10.y); lo.y = rg10.y - hi.y;
            hi.z = tf32hi(rg10.z); lo.z = rg10.z - hi.z;
            hi.w = tf32hi(rg10.w); lo.w = rg10.w - hi.w;
            *(float4*)&Bs_h[gk + 8][gn] = hi;
            *(float4*)&Bs_l[gk + 8][gn] = lo;
            hi.x = tf32hi(rg11.x); lo.x = rg11.x - hi.x;
            hi.y = tf32hi(rg11.y); lo.y = rg11.y - hi.y;
            hi.z = tf32hi(rg11.z); lo.z = rg11.z - hi.z;
            hi.w = tf32hi(rg11.w); lo.w = rg11.w - hi.w;
            *(float4*)&Bs_h[gk + 8][gn + 4] = hi;
            *(float4*)&Bs_l[gk + 8][gn + 4] = lo;
        }
        __syncthreads();

        // Prefetch next stage before compute (latency overlaps mma)
        if (s < 3) {
            const float* ap = aptr + (s + 1) * 16;
            const float* gp = gptr + (size_t)(s + 1) * 16 * 128;
            ra0  = *(const float4*)(ap);
            ra1  = *(const float4*)(ap + 4);
            rg00 = *(const float4*)(gp);
            rg01 = *(const float4*)(gp + 4);
            rg10 = *(const float4*)(gp + (size_t)8 * 128);
            rg11 = *(const float4*)(gp + (size_t)8 * 128 + 4);
        }

        #pragma unroll
        for (int kk = 0; kk < 2; ++kk) {
            const int k0 = kk * 8;
            const int ar = w * 16 + g;
            const uint32_t ah0 = __float_as_uint(As_h[ar][k0 + t]);
            const uint32_t ah1 = __float_as_uint(As_h[ar + 8][k0 + t]);
            const uint32_t ah2 = __float_as_uint(As_h[ar][k0 + t + 4]);
            const uint32_t ah3 = __float_as_uint(As_h[ar + 8][k0 + t + 4]);
            const uint32_t al0 = __float_as_uint(As_l[ar][k0 + t]);
            const uint32_t al1 = __float_as_uint(As_l[ar + 8][k0 + t]);
            const uint32_t al2 = __float_as_uint(As_l[ar][k0 + t + 4]);
            const uint32_t al3 = __float_as_uint(As_l[ar + 8][k0 + t + 4]);
            #pragma unroll
            for (int nt = 0; nt < 16; ++nt) {
                const int n0 = nt * 8;
                const uint32_t bh0 = __float_as_uint(Bs_h[k0 + t][n0 + g]);
                const uint32_t bh1 = __float_as_uint(Bs_h[k0 + t + 4][n0 + g]);
                const uint32_t bl0 = __float_as_uint(Bs_l[k0 + t][n0 + g]);
                const uint32_t bl1 = __float_as_uint(Bs_l[k0 + t + 4][n0 + g]);
                MMA_TF32(acc[nt], ah0, ah1, ah2, ah3, bh0, bh1);
                MMA_TF32(acc[nt], ah0, ah1, ah2, ah3, bl0, bl1);
                MMA_TF32(acc[nt], al0, al1, al2, al3, bh0, bh1);
            }
        }
        __syncthreads();
    }

    // Epilogue: write this split's partial tile.
    // c0,c1 at (row g, cols 2t,2t+1); c2,c3 at (row g+8).
    float* p = part + (size_t)ks * (BB * NN * 128);
    const int r0 = m0 + w * 16 + g;
    const int r1 = r0 + 8;
    #pragma unroll
    for (int nt = 0; nt < 16; ++nt) {
        const int col = nt * 8 + t * 2;
        *(float2*)(p + (size_t)r0 * 128 + col) = make_float2(acc[nt][0], acc[nt][1]);
        *(float2*)(p + (size_t)r1 * 128 + col) = make_float2(acc[nt][2], acc[nt][3]);
    }
}

// ---------------------------------------------------------------------------
// finish: C = sum_ks part[ks] + deg⊗bb + bu   (part is L2-resident)
// ---------------------------------------------------------------------------
__global__ void __launch_bounds__(128) finish_kernel(
    const float* __restrict__ part,
    const float* __restrict__ bb,
    const float* __restrict__ bu,
    const float* __restrict__ deg,
    float* __restrict__ C)
{
    const int t   = blockIdx.x * 128 + threadIdx.x;
    const int row = t >> 5;
    const int c4  = (t & 31) * 4;
    const size_t off = (size_t)row * 128 + c4;

    float4 s = make_float4(0.f, 0.f, 0.f, 0.f);
    #pragma unroll
    for (int ks = 0; ks < SK; ++ks) {
        const float4 v = *(const float4*)(part + (size_t)ks * (BB * NN * 128) + off);
        s.x += v.x; s.y += v.y; s.z += v.z; s.w += v.w;
    }
    const float dg = __ldg(deg + row);
    const float4 bbv = *(const float4*)(bb + c4);
    const float4 buv = *(const float4*)(bu + c4);
    s.x += dg * bbv.x + buv.x;
    s.y += dg * bbv.y + buv.y;
    s.z += dg * bbv.z + buv.z;
    s.w += dg * bbv.w + buv.w;
    *(float4*)(C + off) = s;
}

// ---------------------------------------------------------------------------
// kernel_launch: inputs: h, adj, e, Wm, bm, Wu, bu ; output (B,N,D) fp32
// ---------------------------------------------------------------------------
extern "C" void kernel_launch(void* const* d_in, const int* in_sizes, int n_in,
                              void* d_out, int out_size)
{
    const float* h   = (const float*)d_in[0];
    const float* adj = (const float*)d_in[1];
    const float* e   = (const float*)d_in[2];
    const float* Wm  = (const float*)d_in[3];
    const float* bm  = (const float*)d_in[4];
    const float* Wu  = (const float*)d_in[5];
    const float* bu  = (const float*)d_in[6];
    float* out = (float*)d_out;

    float* xfull; cudaGetSymbolAddress((void**)&xfull, g_xfull);
    float* G;     cudaGetSymbolAddress((void**)&G,     g_G);
    float* bb;    cudaGetSymbolAddress((void**)&bb,    g_bb);
    float* deg;   cudaGetSymbolAddress((void**)&deg,   g_deg);
    float* part;  cudaGetSymbolAddress((void**)&part,  g_part);

    fused_prep_reduce<<<PREP_BLOCKS + BB * NN, 256>>>(
        h, adj, e, Wm, Wu, bm, xfull, deg, G, bb);

    {
        dim3 grid(SK, (BB * NN) / 64);   // (8, 32)
        gemm_mma<<<grid, 128>>>(xfull, G, part);
    }
    finish_kernel<<<512, 128>>>(part, bb, bu, deg, out);
}